// round 1
// baseline (speedup 1.0000x reference)
#include <cuda_runtime.h>
#include <math.h>

#define T_TOK 32768
#define D_DIM 1024
#define F_DIM 2048
#define NE    16
#define NA    (T_TOK * 2)          // total assignments (top-2)
#define CT1   (F_DIM / 64)         // 32 column tiles for gate/up GEMM
#define CT2   (D_DIM / 64)         // 16 column tiles for down GEMM
#define MAXT1 ((NA / 64 + NE) * CT1)   // 33280
#define MAXT2 ((NA / 64 + NE) * CT2)   // 16640

// ------------------- device scratch (no allocation allowed) -------------------
__device__ int   g_counts[NE];
__device__ int   g_offsets[NE + 1];
__device__ int   g_cursor[NE];
__device__ int   g_te[NA];          // per (token,slot): expert id
__device__ float g_tw[NA];          // per (token,slot): combine weight
__device__ int   g_idx[NA];         // per assignment position: token id
__device__ float g_wgt[NA];         // per assignment position: combine weight
__device__ int   g_pos[NA];         // per (token,slot): assignment position
__device__ int   g_tp1[NE + 1];     // tile prefix for gemm1
__device__ int   g_tp2[NE + 1];     // tile prefix for gemm2
__device__ float g_H[(size_t)NA * F_DIM];   // 512 MB: silu(xG)*(xU) per assignment
__device__ float g_Y[(size_t)NA * D_DIM];   // 256 MB: weighted down-proj per assignment

// ------------------- kernel 0: reset counters -------------------
__global__ void k_init() {
    if (threadIdx.x < NE) g_counts[threadIdx.x] = 0;
}

// ------------------- kernel 1: router (logits, softmax, top-2) -------------------
__global__ __launch_bounds__(256) void k_router(const float* __restrict__ x,
                                                const float* __restrict__ rw,
                                                float* __restrict__ logits) {
    int warp = (blockIdx.x * blockDim.x + threadIdx.x) >> 5;
    int lane = threadIdx.x & 31;
    if (warp >= T_TOK) return;
    const float* xr = x + (size_t)warp * D_DIM;

    float acc[NE];
#pragma unroll
    for (int e = 0; e < NE; e++) acc[e] = 0.f;

#pragma unroll
    for (int d0 = 0; d0 < D_DIM; d0 += 128) {
        float4 xv = *reinterpret_cast<const float4*>(xr + d0 + lane * 4);
#pragma unroll
        for (int e = 0; e < NE; e++) {
            float4 wv = *reinterpret_cast<const float4*>(rw + e * D_DIM + d0 + lane * 4);
            acc[e] += xv.x * wv.x + xv.y * wv.y + xv.z * wv.z + xv.w * wv.w;
        }
    }
#pragma unroll
    for (int e = 0; e < NE; e++) {
#pragma unroll
        for (int off = 16; off > 0; off >>= 1)
            acc[e] += __shfl_down_sync(0xffffffffu, acc[e], off);
    }

    if (lane == 0) {
        // raw logits out
        float* lo = logits + (size_t)warp * NE;
#pragma unroll
        for (int e = 0; e < NE; e++) lo[e] = acc[e];

        // softmax
        float m = acc[0];
#pragma unroll
        for (int e = 1; e < NE; e++) m = fmaxf(m, acc[e]);
        float p[NE], s = 0.f;
#pragma unroll
        for (int e = 0; e < NE; e++) { p[e] = __expf(acc[e] - m); s += p[e]; }
        float inv = 1.f / s;

        // top-2 (strict > scan -> lowest index on ties, matching lax.top_k)
        int i1 = 0; float v1 = acc[0];
#pragma unroll
        for (int e = 1; e < NE; e++) if (acc[e] > v1) { v1 = acc[e]; i1 = e; }
        int i2 = -1; float v2 = -1e30f;
#pragma unroll
        for (int e = 0; e < NE; e++) if (e != i1 && acc[e] > v2) { v2 = acc[e]; i2 = e; }

        g_te[2 * warp]     = i1;  g_tw[2 * warp]     = p[i1] * inv;
        g_te[2 * warp + 1] = i2;  g_tw[2 * warp + 1] = p[i2] * inv;
        atomicAdd(&g_counts[i1], 1);
        atomicAdd(&g_counts[i2], 1);
    }
}

// ------------------- kernel 2: offsets / tile prefixes -------------------
__global__ void k_setup() {
    if (threadIdx.x == 0 && blockIdx.x == 0) {
        int off = 0, t1 = 0, t2 = 0;
        for (int e = 0; e < NE; e++) {
            g_offsets[e] = off;
            g_cursor[e]  = off;
            int c = g_counts[e];
            off += c;
            g_tp1[e] = t1;
            g_tp2[e] = t2;
            int rt = (c + 63) >> 6;
            t1 += rt * CT1;
            t2 += rt * CT2;
        }
        g_offsets[NE] = off;
        g_tp1[NE] = t1;
        g_tp2[NE] = t2;
    }
}

// ------------------- kernel 3: scatter tokens into expert segments -------------------
__global__ __launch_bounds__(256) void k_scatter() {
    int t = blockIdx.x * blockDim.x + threadIdx.x;
    if (t >= T_TOK) return;
#pragma unroll
    for (int s = 0; s < 2; s++) {
        int e = g_te[2 * t + s];
        int pos = atomicAdd(&g_cursor[e], 1);
        g_idx[pos] = t;
        g_wgt[pos] = g_tw[2 * t + s];
        g_pos[2 * t + s] = pos;
    }
}

// ------------------- tile id decode helper -------------------
__device__ __forceinline__ int find_expert(const int* prefix, int b) {
    if (b >= prefix[NE]) return -1;
#pragma unroll
    for (int i = 0; i < NE; i++)
        if (b >= prefix[i] && b < prefix[i + 1]) return i;
    return -1;
}

// ------------------- kernel 4: fused gate/up GEMM + SiLU -------------------
// H[pos, f] = silu(x[tok] @ gate_w[e][:, f]) * (x[tok] @ up_w[e][:, f])
__global__ __launch_bounds__(256) void k_gemm1(const float* __restrict__ x,
                                               const float* __restrict__ gw,
                                               const float* __restrict__ uw) {
    __shared__ float As[64][17];
    __shared__ float Bg[16][64];
    __shared__ float Bu[16][64];
    __shared__ int sh[3];

    int tid = threadIdx.x;
    if (tid == 0) {
        int e = find_expert(g_tp1, blockIdx.x);
        sh[0] = e;
        if (e >= 0) {
            int local = blockIdx.x - g_tp1[e];
            sh[1] = local / CT1;     // row tile
            sh[2] = local % CT1;     // col tile
        }
    }
    __syncthreads();
    int e = sh[0];
    if (e < 0) return;
    int rt = sh[1], ct = sh[2];
    int off = g_offsets[e];
    int n   = g_offsets[e + 1] - off;
    int row0 = rt << 6;

    // A load plan: 4 elements / thread / k-step
    int ak = tid & 15;
    const float* aptr[4];
    bool aval[4];
#pragma unroll
    for (int i = 0; i < 4; i++) {
        int ar = (tid + i * 256) >> 4;
        int r = row0 + ar;
        bool v = (r < n);
        int tok = v ? g_idx[off + r] : 0;
        aval[i] = v;
        aptr[i] = x + (size_t)tok * D_DIM + ak;
    }
    // B load plan
    int bk = tid >> 6;
    int bn = tid & 63;
    const float* gptr = gw + (size_t)e * D_DIM * F_DIM + (size_t)bk * F_DIM + (ct << 6) + bn;
    const float* uptr = uw + (size_t)e * D_DIM * F_DIM + (size_t)bk * F_DIM + (ct << 6) + bn;

    int tx = tid & 15, ty = tid >> 4;
    float accG[4][4], accU[4][4];
#pragma unroll
    for (int i = 0; i < 4; i++)
#pragma unroll
        for (int j = 0; j < 4; j++) { accG[i][j] = 0.f; accU[i][j] = 0.f; }

    for (int k0 = 0; k0 < D_DIM; k0 += 16) {
#pragma unroll
        for (int i = 0; i < 4; i++) {
            int ar = (tid + i * 256) >> 4;
            As[ar][ak] = aval[i] ? aptr[i][k0] : 0.f;
        }
#pragma unroll
        for (int i = 0; i < 4; i++) {
            Bg[bk + i * 4][bn] = gptr[(size_t)(k0 + i * 4) * F_DIM];
            Bu[bk + i * 4][bn] = uptr[(size_t)(k0 + i * 4) * F_DIM];
        }
        __syncthreads();
#pragma unroll
        for (int kk = 0; kk < 16; kk++) {
            float a[4];
#pragma unroll
            for (int i = 0; i < 4; i++) a[i] = As[ty * 4 + i][kk];
            float4 bg = *reinterpret_cast<const float4*>(&Bg[kk][tx * 4]);
            float4 bu = *reinterpret_cast<const float4*>(&Bu[kk][tx * 4]);
#pragma unroll
            for (int i = 0; i < 4; i++) {
                accG[i][0] += a[i] * bg.x; accG[i][1] += a[i] * bg.y;
                accG[i][2] += a[i] * bg.z; accG[i][3] += a[i] * bg.w;
                accU[i][0] += a[i] * bu.x; accU[i][1] += a[i] * bu.y;
                accU[i][2] += a[i] * bu.z; accU[i][3] += a[i] * bu.w;
            }
        }
        __syncthreads();
    }

#pragma unroll
    for (int i = 0; i < 4; i++) {
        int r = row0 + ty * 4 + i;
        if (r < n) {
            float4 hv;
            float g, u;
            g = accG[i][0]; u = accU[i][0]; hv.x = g * (1.f / (1.f + __expf(-g))) * u;
            g = accG[i][1]; u = accU[i][1]; hv.y = g * (1.f / (1.f + __expf(-g))) * u;
            g = accG[i][2]; u = accU[i][2]; hv.z = g * (1.f / (1.f + __expf(-g))) * u;
            g = accG[i][3]; u = accU[i][3]; hv.w = g * (1.f / (1.f + __expf(-g))) * u;
            *reinterpret_cast<float4*>(&g_H[(size_t)(off + r) * F_DIM + (ct << 6) + tx * 4]) = hv;
        }
    }
}

// ------------------- kernel 5: down GEMM (weighted) -------------------
// Y[pos, d] = w[pos] * (H[pos] @ down_w[e][:, d])
__global__ __launch_bounds__(256) void k_gemm2(const float* __restrict__ dw) {
    __shared__ float As[64][17];
    __shared__ float Bd[16][64];
    __shared__ int sh[3];

    int tid = threadIdx.x;
    if (tid == 0) {
        int e = find_expert(g_tp2, blockIdx.x);
        sh[0] = e;
        if (e >= 0) {
            int local = blockIdx.x - g_tp2[e];
            sh[1] = local / CT2;
            sh[2] = local % CT2;
        }
    }
    __syncthreads();
    int e = sh[0];
    if (e < 0) return;
    int rt = sh[1], ct = sh[2];
    int off = g_offsets[e];
    int n   = g_offsets[e + 1] - off;
    int row0 = rt << 6;

    int ak = tid & 15;
    const float* aptr[4];
    bool aval[4];
#pragma unroll
    for (int i = 0; i < 4; i++) {
        int ar = (tid + i * 256) >> 4;
        int r = row0 + ar;
        bool v = (r < n);
        aval[i] = v;
        aptr[i] = g_H + (size_t)(v ? (off + r) : 0) * F_DIM + ak;
    }
    int bk = tid >> 6;
    int bn = tid & 63;
    const float* dptr = dw + (size_t)e * F_DIM * D_DIM + (size_t)bk * D_DIM + (ct << 6) + bn;

    int tx = tid & 15, ty = tid >> 4;
    float acc[4][4];
#pragma unroll
    for (int i = 0; i < 4; i++)
#pragma unroll
        for (int j = 0; j < 4; j++) acc[i][j] = 0.f;

    for (int k0 = 0; k0 < F_DIM; k0 += 16) {
#pragma unroll
        for (int i = 0; i < 4; i++) {
            int ar = (tid + i * 256) >> 4;
            As[ar][ak] = aval[i] ? aptr[i][k0] : 0.f;
        }
#pragma unroll
        for (int i = 0; i < 4; i++)
            Bd[bk + i * 4][bn] = dptr[(size_t)(k0 + i * 4) * D_DIM];
        __syncthreads();
#pragma unroll
        for (int kk = 0; kk < 16; kk++) {
            float a[4];
#pragma unroll
            for (int i = 0; i < 4; i++) a[i] = As[ty * 4 + i][kk];
            float4 b = *reinterpret_cast<const float4*>(&Bd[kk][tx * 4]);
#pragma unroll
            for (int i = 0; i < 4; i++) {
                acc[i][0] += a[i] * b.x; acc[i][1] += a[i] * b.y;
                acc[i][2] += a[i] * b.z; acc[i][3] += a[i] * b.w;
            }
        }
        __syncthreads();
    }

#pragma unroll
    for (int i = 0; i < 4; i++) {
        int r = row0 + ty * 4 + i;
        if (r < n) {
            float w = g_wgt[off + r];
            float4 yv;
            yv.x = w * acc[i][0]; yv.y = w * acc[i][1];
            yv.z = w * acc[i][2]; yv.w = w * acc[i][3];
            *reinterpret_cast<float4*>(&g_Y[(size_t)(off + r) * D_DIM + (ct << 6) + tx * 4]) = yv;
        }
    }
}

// ------------------- kernel 6: combine the two expert contributions -------------------
__global__ __launch_bounds__(256) void k_combine(float* __restrict__ out) {
    int gid = blockIdx.x * blockDim.x + threadIdx.x;   // over T*D/4 float4s
    int t = gid >> 8;                                   // 256 float4 per token
    int c = gid & 255;
    if (t >= T_TOK) return;
    int p1 = g_pos[2 * t], p2 = g_pos[2 * t + 1];
    const float4* y = reinterpret_cast<const float4*>(g_Y);
    float4 a = y[(size_t)p1 * (D_DIM / 4) + c];
    float4 b = y[(size_t)p2 * (D_DIM / 4) + c];
    float4 o;
    o.x = a.x + b.x; o.y = a.y + b.y; o.z = a.z + b.z; o.w = a.w + b.w;
    reinterpret_cast<float4*>(out)[gid] = o;
}

// ------------------- launch -------------------
extern "C" void kernel_launch(void* const* d_in, const int* in_sizes, int n_in,
                              void* d_out, int out_size) {
    const float* x  = (const float*)d_in[0];   // [T, D]
    const float* rw = (const float*)d_in[1];   // [E, D]
    const float* gw = (const float*)d_in[2];   // [E, D, F]
    const float* uw = (const float*)d_in[3];   // [E, D, F]
    const float* dw = (const float*)d_in[4];   // [E, F, D]
    float* out    = (float*)d_out;                       // [T, D]
    float* logits = out + (size_t)T_TOK * D_DIM;         // [T, E]

    k_init<<<1, 32>>>();
    k_router<<<T_TOK / 8, 256>>>(x, rw, logits);
    k_setup<<<1, 1>>>();
    k_scatter<<<T_TOK / 256, 256>>>();
    k_gemm1<<<MAXT1, 256>>>(x, gw, uw);
    k_gemm2<<<MAXT2, 256>>>(dw);
    k_combine<<<(T_TOK * D_DIM / 4) / 256, 256>>>(out);
}

// round 3
// speedup vs baseline: 7.1630x; 7.1630x over previous
#include <cuda_runtime.h>
#include <cuda_fp16.h>
#include <cstdint>
#include <math.h>

#define T_TOK 32768
#define D_DIM 1024
#define F_DIM 2048
#define NE    16
#define NA    (T_TOK * 2)
#define ROWT  128
#define CT1   32                       // F/64 col tiles (gemm1)
#define CT2   8                        // D/128 col tiles (gemm2)
#define KT1   32                       // D/32
#define KT2   64                       // F/32
#define MAXT1 ((NA / ROWT + NE) * CT1) // 8704
#define MAXT2 ((NA / ROWT + NE) * CT2) // 2176

// ---------------- device scratch ----------------
__device__ int    g_counts[NE];
__device__ int    g_offsets[NE + 1];
__device__ int    g_cursor[NE];
__device__ int    g_te[NA];
__device__ float  g_tw[NA];
__device__ int    g_idx[NA];
__device__ float  g_wgt[NA];
__device__ int    g_pos[NA];
__device__ int    g_tp1[NE + 1];
__device__ int    g_tp2[NE + 1];
__device__ __half g_xh[(size_t)T_TOK * D_DIM];
__device__ __half g_gwh[(size_t)NE * D_DIM * F_DIM];   // [E][D][F]
__device__ __half g_uwh[(size_t)NE * D_DIM * F_DIM];   // [E][D][F]
__device__ __half g_dwh[(size_t)NE * F_DIM * D_DIM];   // [E][F][D]
__device__ __half g_H[(size_t)(NA + ROWT) * F_DIM];
__device__ float  g_Y[(size_t)(NA + ROWT) * D_DIM];

// ---------------- helpers ----------------
__device__ __forceinline__ uint32_t smem_u32(const void* p) {
    uint32_t a;
    asm("{ .reg .u64 t; cvta.to.shared.u64 t, %1; cvt.u32.u64 %0, t; }" : "=r"(a) : "l"(p));
    return a;
}
__device__ __forceinline__ void cpa16(uint32_t s, const void* g) {
    asm volatile("cp.async.cg.shared.global [%0], [%1], 16;" :: "r"(s), "l"(__cvta_generic_to_global(g)) : "memory");
}
#define CP_COMMIT() asm volatile("cp.async.commit_group;" ::: "memory")
#define CP_WAIT(n)  asm volatile("cp.async.wait_group %0;" :: "n"(n) : "memory")

__device__ __forceinline__ void ldsm4(uint32_t* r, uint32_t a) {
    asm volatile("ldmatrix.sync.aligned.m8n8.x4.shared.b16 {%0,%1,%2,%3}, [%4];"
                 : "=r"(r[0]), "=r"(r[1]), "=r"(r[2]), "=r"(r[3]) : "r"(a));
}
__device__ __forceinline__ void ldsm4t(uint32_t* r, uint32_t a) {
    asm volatile("ldmatrix.sync.aligned.m8n8.x4.trans.shared.b16 {%0,%1,%2,%3}, [%4];"
                 : "=r"(r[0]), "=r"(r[1]), "=r"(r[2]), "=r"(r[3]) : "r"(a));
}
__device__ __forceinline__ void mma16816(float* d, const uint32_t* a, const uint32_t* b) {
    asm volatile("mma.sync.aligned.m16n8k16.row.col.f32.f16.f16.f32 "
                 "{%0,%1,%2,%3},{%4,%5,%6,%7},{%8,%9},{%0,%1,%2,%3};"
                 : "+f"(d[0]), "+f"(d[1]), "+f"(d[2]), "+f"(d[3])
                 : "r"(a[0]), "r"(a[1]), "r"(a[2]), "r"(a[3]), "r"(b[0]), "r"(b[1]));
}

// ---------------- routing ----------------
__global__ void k_init() { if (threadIdx.x < NE) g_counts[threadIdx.x] = 0; }

__global__ __launch_bounds__(256) void k_router(const float* __restrict__ x,
                                                const float* __restrict__ rw,
                                                float* __restrict__ logits) {
    int warp = (blockIdx.x * blockDim.x + threadIdx.x) >> 5;
    int lane = threadIdx.x & 31;
    if (warp >= T_TOK) return;
    const float* xr = x + (size_t)warp * D_DIM;
    float acc[NE];
#pragma unroll
    for (int e = 0; e < NE; e++) acc[e] = 0.f;
#pragma unroll
    for (int d0 = 0; d0 < D_DIM; d0 += 128) {
        float4 xv = *reinterpret_cast<const float4*>(xr + d0 + lane * 4);
#pragma unroll
        for (int e = 0; e < NE; e++) {
            float4 wv = *reinterpret_cast<const float4*>(rw + e * D_DIM + d0 + lane * 4);
            acc[e] += xv.x * wv.x + xv.y * wv.y + xv.z * wv.z + xv.w * wv.w;
        }
    }
#pragma unroll
    for (int e = 0; e < NE; e++)
#pragma unroll
        for (int off = 16; off > 0; off >>= 1)
            acc[e] += __shfl_down_sync(0xffffffffu, acc[e], off);
    if (lane == 0) {
        float* lo = logits + (size_t)warp * NE;
#pragma unroll
        for (int e = 0; e < NE; e++) lo[e] = acc[e];
        float m = acc[0];
#pragma unroll
        for (int e = 1; e < NE; e++) m = fmaxf(m, acc[e]);
        float p[NE], s = 0.f;
#pragma unroll
        for (int e = 0; e < NE; e++) { p[e] = __expf(acc[e] - m); s += p[e]; }
        float inv = 1.f / s;
        int i1 = 0; float v1 = acc[0];
#pragma unroll
        for (int e = 1; e < NE; e++) if (acc[e] > v1) { v1 = acc[e]; i1 = e; }
        int i2 = -1; float v2 = -1e30f;
#pragma unroll
        for (int e = 0; e < NE; e++) if (e != i1 && acc[e] > v2) { v2 = acc[e]; i2 = e; }
        g_te[2 * warp]     = i1; g_tw[2 * warp]     = p[i1] * inv;
        g_te[2 * warp + 1] = i2; g_tw[2 * warp + 1] = p[i2] * inv;
        atomicAdd(&g_counts[i1], 1);
        atomicAdd(&g_counts[i2], 1);
    }
}

__global__ void k_setup() {
    if (threadIdx.x == 0 && blockIdx.x == 0) {
        int off = 0, t1 = 0, t2 = 0;
        for (int e = 0; e < NE; e++) {
            g_offsets[e] = off; g_cursor[e] = off;
            int c = g_counts[e]; off += c;
            g_tp1[e] = t1; g_tp2[e] = t2;
            int rt = (c + ROWT - 1) >> 7;
            t1 += rt * CT1; t2 += rt * CT2;
        }
        g_offsets[NE] = off; g_tp1[NE] = t1; g_tp2[NE] = t2;
    }
}

__global__ __launch_bounds__(256) void k_scatter() {
    int t = blockIdx.x * blockDim.x + threadIdx.x;
    if (t >= T_TOK) return;
#pragma unroll
    for (int s = 0; s < 2; s++) {
        int e = g_te[2 * t + s];
        int pos = atomicAdd(&g_cursor[e], 1);
        g_idx[pos] = t;
        g_wgt[pos] = g_tw[2 * t + s];
        g_pos[2 * t + s] = pos;
    }
}

// ---------------- fp32 -> fp16 convert (x and the three weight tensors; all 33.5M elems) ----------------
__global__ __launch_bounds__(256) void k_cvt(const float4* __restrict__ src, int which) {
    __half* dst = (which == 0) ? g_xh : (which == 1) ? g_gwh : (which == 2) ? g_uwh : g_dwh;
    size_t i = (size_t)blockIdx.x * 256 + threadIdx.x;
    float4 v = src[i];
    __half2 h0 = __floats2half2_rn(v.x, v.y);
    __half2 h1 = __floats2half2_rn(v.z, v.w);
    uint2 o = make_uint2(*reinterpret_cast<uint32_t*>(&h0), *reinterpret_cast<uint32_t*>(&h1));
    reinterpret_cast<uint2*>(dst)[i] = o;
}

// ---------------- GEMM1: H = silu(X Gw) * (X Uw) ----------------
// CTA: 128 rows x 64 f-cols (both gate & up). 8 warps = 2(M) x 4(N); warp tile 64x16.
__global__ __launch_bounds__(256, 2) void k_mma1() {
    __shared__ __align__(16) __half As[2][128][40];
    __shared__ __align__(16) __half Bgs[2][32][72];
    __shared__ __align__(16) __half Bus[2][32][72];
    __shared__ int info[3];

    int tid = threadIdx.x, w = tid >> 5, l = tid & 31;
    if (tid == 0) {
        int b = blockIdx.x, e = -1;
        if (b < g_tp1[NE]) {
#pragma unroll
            for (int i = 0; i < NE; i++) if (b < g_tp1[i + 1]) { e = i; break; }
        }
        info[0] = e;
        if (e >= 0) { int t = b - g_tp1[e]; info[1] = (t >> 5) << 7; info[2] = (t & 31) << 6; }
    }
    __syncthreads();
    int e = info[0];
    if (e < 0) return;
    int row0 = info[1], col0 = info[2];
    int off = g_offsets[e], n = g_offsets[e + 1] - off;

    // A gather plan (2 chunks/thread)
    const __half* srcA[2]; uint32_t dstA[2];
#pragma unroll
    for (int i = 0; i < 2; i++) {
        int id = tid + i * 256, ar = id >> 2, ch = id & 3;
        int r = row0 + ar; if (r > n - 1) r = n - 1;
        srcA[i] = g_xh + (size_t)g_idx[off + r] * D_DIM + ch * 8;
        dstA[i] = smem_u32(&As[0][0][0]) + ar * 80 + ch * 16;
    }
    int br = tid >> 3, bc = tid & 7;
    const __half* srcG = g_gwh + ((size_t)e * D_DIM + br) * F_DIM + col0 + bc * 8;
    const __half* srcU = g_uwh + ((size_t)e * D_DIM + br) * F_DIM + col0 + bc * 8;
    uint32_t dstG = smem_u32(&Bgs[0][0][0]) + br * 144 + bc * 16;
    uint32_t dstU = smem_u32(&Bus[0][0][0]) + br * 144 + bc * 16;

    auto load = [&](int kt) {
        int s = kt & 1;
#pragma unroll
        for (int i = 0; i < 2; i++) cpa16(dstA[i] + s * 10240, srcA[i] + kt * 32);
        cpa16(dstG + s * 4608, srcG + (size_t)kt * 32 * F_DIM);
        cpa16(dstU + s * 4608, srcU + (size_t)kt * 32 * F_DIM);
        CP_COMMIT();
    };
    load(0); load(1);

    float cg[4][2][4], cu[4][2][4];
#pragma unroll
    for (int mi = 0; mi < 4; mi++)
#pragma unroll
        for (int ni = 0; ni < 2; ni++)
#pragma unroll
            for (int j = 0; j < 4; j++) { cg[mi][ni][j] = 0.f; cu[mi][ni][j] = 0.f; }

    uint32_t aS = smem_u32(&As[0][0][0]);
    uint32_t gS = smem_u32(&Bgs[0][0][0]);
    uint32_t uS = smem_u32(&Bus[0][0][0]);
    int wm = w >> 2, wn = w & 3;
    int lr = l & 15, lc = l >> 4;

    for (int kt = 0; kt < KT1; kt++) {
        if (kt < KT1 - 1) CP_WAIT(1); else CP_WAIT(0);
        __syncthreads();
        int s = kt & 1;
        uint32_t ab = aS + s * 10240, gb = gS + s * 4608, ub = uS + s * 4608;
#pragma unroll
        for (int ks = 0; ks < 2; ks++) {
            uint32_t a[4][4], bg[4], bu[4];
#pragma unroll
            for (int mi = 0; mi < 4; mi++)
                ldsm4(a[mi], ab + (wm * 64 + mi * 16 + lr) * 80 + (ks * 16 + lc * 8) * 2);
            ldsm4t(bg, gb + (ks * 16 + lr) * 144 + (wn * 16 + lc * 8) * 2);
            ldsm4t(bu, ub + (ks * 16 + lr) * 144 + (wn * 16 + lc * 8) * 2);
#pragma unroll
            for (int mi = 0; mi < 4; mi++)
#pragma unroll
                for (int ni = 0; ni < 2; ni++) {
                    mma16816(cg[mi][ni], a[mi], &bg[2 * ni]);
                    mma16816(cu[mi][ni], a[mi], &bu[2 * ni]);
                }
        }
        __syncthreads();
        if (kt + 2 < KT1) load(kt + 2);
    }

    // epilogue: h = silu(g) * u, fp16 out
#pragma unroll
    for (int mi = 0; mi < 4; mi++) {
        int rl = row0 + wm * 64 + mi * 16 + (l >> 2);
        int rh = rl + 8;
#pragma unroll
        for (int ni = 0; ni < 2; ni++) {
            int c = col0 + wn * 16 + ni * 8 + 2 * (l & 3);
            float g0 = cg[mi][ni][0], g1 = cg[mi][ni][1], g2 = cg[mi][ni][2], g3 = cg[mi][ni][3];
            float h0 = g0 * __fdividef(1.f, 1.f + __expf(-g0)) * cu[mi][ni][0];
            float h1 = g1 * __fdividef(1.f, 1.f + __expf(-g1)) * cu[mi][ni][1];
            float h2 = g2 * __fdividef(1.f, 1.f + __expf(-g2)) * cu[mi][ni][2];
            float h3 = g3 * __fdividef(1.f, 1.f + __expf(-g3)) * cu[mi][ni][3];
            if (rl < n) *reinterpret_cast<__half2*>(&g_H[(size_t)(off + rl) * F_DIM + c]) = __floats2half2_rn(h0, h1);
            if (rh < n) *reinterpret_cast<__half2*>(&g_H[(size_t)(off + rh) * F_DIM + c]) = __floats2half2_rn(h2, h3);
        }
    }
}

// ---------------- GEMM2: Y = w * (H Dw) ----------------
// CTA: 128 rows x 128 d-cols. 8 warps = 2(M) x 4(N); warp tile 64x32.
__global__ __launch_bounds__(256, 2) void k_mma2() {
    __shared__ __align__(16) __half As[2][128][40];
    __shared__ __align__(16) __half Bs[2][32][136];
    __shared__ int info[3];

    int tid = threadIdx.x, w = tid >> 5, l = tid & 31;
    if (tid == 0) {
        int b = blockIdx.x, e = -1;
        if (b < g_tp2[NE]) {
#pragma unroll
            for (int i = 0; i < NE; i++) if (b < g_tp2[i + 1]) { e = i; break; }
        }
        info[0] = e;
        if (e >= 0) { int t = b - g_tp2[e]; info[1] = (t >> 3) << 7; info[2] = (t & 7) << 7; }
    }
    __syncthreads();
    int e = info[0];
    if (e < 0) return;
    int row0 = info[1], col0 = info[2];
    int off = g_offsets[e], n = g_offsets[e + 1] - off;

    const __half* srcA[2]; uint32_t dstA[2];
#pragma unroll
    for (int i = 0; i < 2; i++) {
        int id = tid + i * 256, ar = id >> 2, ch = id & 3;
        int r = row0 + ar; if (r > n - 1) r = n - 1;
        srcA[i] = g_H + (size_t)(off + r) * F_DIM + ch * 8;
        dstA[i] = smem_u32(&As[0][0][0]) + ar * 80 + ch * 16;
    }
    const __half* srcB[2]; uint32_t dstB[2];
#pragma unroll
    for (int i = 0; i < 2; i++) {
        int id = tid + i * 256, brw = id >> 4, ch = id & 15;
        srcB[i] = g_dwh + ((size_t)e * F_DIM + brw) * D_DIM + col0 + ch * 8;
        dstB[i] = smem_u32(&Bs[0][0][0]) + brw * 272 + ch * 16;
    }

    auto load = [&](int kt) {
        int s = kt & 1;
#pragma unroll
        for (int i = 0; i < 2; i++) cpa16(dstA[i] + s * 10240, srcA[i] + kt * 32);
#pragma unroll
        for (int i = 0; i < 2; i++) cpa16(dstB[i] + s * 8704, srcB[i] + (size_t)kt * 32 * D_DIM);
        CP_COMMIT();
    };
    load(0); load(1);

    float cc[4][4][4];
#pragma unroll
    for (int mi = 0; mi < 4; mi++)
#pragma unroll
        for (int ni = 0; ni < 4; ni++)
#pragma unroll
            for (int j = 0; j < 4; j++) cc[mi][ni][j] = 0.f;

    uint32_t aS = smem_u32(&As[0][0][0]);
    uint32_t bS = smem_u32(&Bs[0][0][0]);
    int wm = w >> 2, wn = w & 3;
    int lr = l & 15, lc = l >> 4;

    for (int kt = 0; kt < KT2; kt++) {
        if (kt < KT2 - 1) CP_WAIT(1); else CP_WAIT(0);
        __syncthreads();
        int s = kt & 1;
        uint32_t ab = aS + s * 10240, bb = bS + s * 8704;
#pragma unroll
        for (int ks = 0; ks < 2; ks++) {
            uint32_t a[4][4], bf[2][4];
#pragma unroll
            for (int mi = 0; mi < 4; mi++)
                ldsm4(a[mi], ab + (wm * 64 + mi * 16 + lr) * 80 + (ks * 16 + lc * 8) * 2);
#pragma unroll
            for (int nf = 0; nf < 2; nf++)
                ldsm4t(bf[nf], bb + (ks * 16 + lr) * 272 + (wn * 32 + nf * 16 + lc * 8) * 2);
#pragma unroll
            for (int mi = 0; mi < 4; mi++)
#pragma unroll
                for (int ni = 0; ni < 4; ni++)
                    mma16816(cc[mi][ni], a[mi], &bf[ni >> 1][2 * (ni & 1)]);
        }
        __syncthreads();
        if (kt + 2 < KT2) load(kt + 2);
    }

#pragma unroll
    for (int mi = 0; mi < 4; mi++) {
        int rl = row0 + wm * 64 + mi * 16 + (l >> 2);
        int rh = rl + 8;
        float wl = (rl < n) ? g_wgt[off + rl] : 0.f;
        float wh = (rh < n) ? g_wgt[off + rh] : 0.f;
#pragma unroll
        for (int ni = 0; ni < 4; ni++) {
            int c = col0 + wn * 32 + ni * 8 + 2 * (l & 3);
            if (rl < n) {
                float2 v = make_float2(wl * cc[mi][ni][0], wl * cc[mi][ni][1]);
                *reinterpret_cast<float2*>(&g_Y[(size_t)(off + rl) * D_DIM + c]) = v;
            }
            if (rh < n) {
                float2 v = make_float2(wh * cc[mi][ni][2], wh * cc[mi][ni][3]);
                *reinterpret_cast<float2*>(&g_Y[(size_t)(off + rh) * D_DIM + c]) = v;
            }
        }
    }
}

// ---------------- combine ----------------
__global__ __launch_bounds__(256) void k_combine(float* __restrict__ out) {
    int gid = blockIdx.x * blockDim.x + threadIdx.x;
    int t = gid >> 8, c = gid & 255;
    if (t >= T_TOK) return;
    int p1 = g_pos[2 * t], p2 = g_pos[2 * t + 1];
    const float4* y = reinterpret_cast<const float4*>(g_Y);
    float4 a = y[(size_t)p1 * (D_DIM / 4) + c];
    float4 b = y[(size_t)p2 * (D_DIM / 4) + c];
    float4 o;
    o.x = a.x + b.x; o.y = a.y + b.y; o.z = a.z + b.z; o.w = a.w + b.w;
    reinterpret_cast<float4*>(out)[gid] = o;
}

// ---------------- launch ----------------
extern "C" void kernel_launch(void* const* d_in, const int* in_sizes, int n_in,
                              void* d_out, int out_size) {
    const float* x  = (const float*)d_in[0];
    const float* rw = (const float*)d_in[1];
    const float* gw = (const float*)d_in[2];
    const float* uw = (const float*)d_in[3];
    const float* dw = (const float*)d_in[4];
    float* out    = (float*)d_out;
    float* logits = out + (size_t)T_TOK * D_DIM;

    k_init<<<1, 32>>>();
    k_router<<<T_TOK / 8, 256>>>(x, rw, logits);
    k_setup<<<1, 1>>>();
    k_scatter<<<T_TOK / 256, 256>>>();

    // all four tensors are 33.5M elements -> same grid
    k_cvt<<<32768, 256>>>((const float4*)x, 0);
    k_cvt<<<32768, 256>>>((const float4*)gw, 1);
    k_cvt<<<32768, 256>>>((const float4*)uw, 2);
    k_cvt<<<32768, 256>>>((const float4*)dw, 3);

    k_mma1<<<MAXT1, 256>>>();
    k_mma2<<<MAXT2, 256>>>();
    k_combine<<<(T_TOK * D_DIM / 4) / 256, 256>>>(out);
}

// round 4
// speedup vs baseline: 7.4669x; 1.0424x over previous
#include <cuda_runtime.h>
#include <cuda_fp16.h>
#include <cstdint>
#include <math.h>

#define T_TOK 32768
#define D_DIM 1024
#define F_DIM 2048
#define NE    16
#define NA    (T_TOK * 2)
#define ROWT  128
#define CT1   32                       // F/64 col tiles (gemm1)
#define CT2   8                        // D/128 col tiles (gemm2)
#define KT1   32                       // D/32
#define KT2   64                       // F/32
#define MAXT1 ((NA / ROWT + NE) * CT1) // 8704
#define MAXT2 ((NA / ROWT + NE) * CT2) // 2176

#define STG1  19456                    // A 10240 + Bg 4608 + Bu 4608
#define STG2  18944                    // A 10240 + B 8704
#define SMEM1 (3 * STG1)               // 58368
#define SMEM2 (3 * STG2)               // 56832

// ---------------- device scratch ----------------
__device__ int    g_counts[NE];
__device__ int    g_offsets[NE + 1];
__device__ int    g_cursor[NE];
__device__ int    g_te[NA];
__device__ float  g_tw[NA];
__device__ int    g_idx[NA];
__device__ float  g_wgt[NA];
__device__ int    g_pos[NA];
__device__ int    g_tp1[NE + 1];
__device__ int    g_tp2[NE + 1];
__device__ __half g_xh[(size_t)T_TOK * D_DIM];
__device__ __half g_gwh[(size_t)NE * D_DIM * F_DIM];   // [E][D][F]
__device__ __half g_uwh[(size_t)NE * D_DIM * F_DIM];   // [E][D][F]
__device__ __half g_dwh[(size_t)NE * F_DIM * D_DIM];   // [E][F][D]
__device__ __half g_H[(size_t)(NA + ROWT) * F_DIM];
__device__ float  g_Y[(size_t)(NA + ROWT) * D_DIM];

// ---------------- helpers ----------------
__device__ __forceinline__ uint32_t smem_u32(const void* p) {
    uint32_t a;
    asm("{ .reg .u64 t; cvta.to.shared.u64 t, %1; cvt.u32.u64 %0, t; }" : "=r"(a) : "l"(p));
    return a;
}
__device__ __forceinline__ void cpa16(uint32_t s, const void* g) {
    asm volatile("cp.async.cg.shared.global [%0], [%1], 16;" :: "r"(s), "l"(__cvta_generic_to_global(g)) : "memory");
}
#define CP_COMMIT() asm volatile("cp.async.commit_group;" ::: "memory")
#define CP_WAIT(n)  asm volatile("cp.async.wait_group %0;" :: "n"(n) : "memory")

__device__ __forceinline__ void ldsm4(uint32_t* r, uint32_t a) {
    asm volatile("ldmatrix.sync.aligned.m8n8.x4.shared.b16 {%0,%1,%2,%3}, [%4];"
                 : "=r"(r[0]), "=r"(r[1]), "=r"(r[2]), "=r"(r[3]) : "r"(a));
}
__device__ __forceinline__ void ldsm4t(uint32_t* r, uint32_t a) {
    asm volatile("ldmatrix.sync.aligned.m8n8.x4.trans.shared.b16 {%0,%1,%2,%3}, [%4];"
                 : "=r"(r[0]), "=r"(r[1]), "=r"(r[2]), "=r"(r[3]) : "r"(a));
}
__device__ __forceinline__ void mma16816(float* d, const uint32_t* a, const uint32_t* b) {
    asm volatile("mma.sync.aligned.m16n8k16.row.col.f32.f16.f16.f32 "
                 "{%0,%1,%2,%3},{%4,%5,%6,%7},{%8,%9},{%0,%1,%2,%3};"
                 : "+f"(d[0]), "+f"(d[1]), "+f"(d[2]), "+f"(d[3])
                 : "r"(a[0]), "r"(a[1]), "r"(a[2]), "r"(a[3]), "r"(b[0]), "r"(b[1]));
}

// ---------------- routing (+ fused fp16 convert of x) ----------------
__global__ void k_init() { if (threadIdx.x < NE) g_counts[threadIdx.x] = 0; }

__global__ __launch_bounds__(256) void k_router(const float* __restrict__ x,
                                                const float* __restrict__ rw,
                                                float* __restrict__ logits) {
    int warp = (blockIdx.x * blockDim.x + threadIdx.x) >> 5;
    int lane = threadIdx.x & 31;
    if (warp >= T_TOK) return;
    const float* xr = x + (size_t)warp * D_DIM;
    __half* xh = g_xh + (size_t)warp * D_DIM;
    float acc[NE];
#pragma unroll
    for (int e = 0; e < NE; e++) acc[e] = 0.f;
#pragma unroll
    for (int d0 = 0; d0 < D_DIM; d0 += 128) {
        float4 xv = *reinterpret_cast<const float4*>(xr + d0 + lane * 4);
        // fused conversion: write fp16 copy of x
        __half2 h0 = __floats2half2_rn(xv.x, xv.y);
        __half2 h1 = __floats2half2_rn(xv.z, xv.w);
        *reinterpret_cast<uint2*>(xh + d0 + lane * 4) =
            make_uint2(*reinterpret_cast<uint32_t*>(&h0), *reinterpret_cast<uint32_t*>(&h1));
#pragma unroll
        for (int e = 0; e < NE; e++) {
            float4 wv = *reinterpret_cast<const float4*>(rw + e * D_DIM + d0 + lane * 4);
            acc[e] += xv.x * wv.x + xv.y * wv.y + xv.z * wv.z + xv.w * wv.w;
        }
    }
#pragma unroll
    for (int e = 0; e < NE; e++)
#pragma unroll
        for (int off = 16; off > 0; off >>= 1)
            acc[e] += __shfl_down_sync(0xffffffffu, acc[e], off);
    if (lane == 0) {
        float* lo = logits + (size_t)warp * NE;
#pragma unroll
        for (int e = 0; e < NE; e++) lo[e] = acc[e];
        float m = acc[0];
#pragma unroll
        for (int e = 1; e < NE; e++) m = fmaxf(m, acc[e]);
        float p[NE], s = 0.f;
#pragma unroll
        for (int e = 0; e < NE; e++) { p[e] = __expf(acc[e] - m); s += p[e]; }
        float inv = 1.f / s;
        int i1 = 0; float v1 = acc[0];
#pragma unroll
        for (int e = 1; e < NE; e++) if (acc[e] > v1) { v1 = acc[e]; i1 = e; }
        int i2 = -1; float v2 = -1e30f;
#pragma unroll
        for (int e = 0; e < NE; e++) if (e != i1 && acc[e] > v2) { v2 = acc[e]; i2 = e; }
        g_te[2 * warp]     = i1; g_tw[2 * warp]     = p[i1] * inv;
        g_te[2 * warp + 1] = i2; g_tw[2 * warp + 1] = p[i2] * inv;
        atomicAdd(&g_counts[i1], 1);
        atomicAdd(&g_counts[i2], 1);
    }
}

__global__ void k_setup() {
    if (threadIdx.x == 0 && blockIdx.x == 0) {
        int off = 0, t1 = 0, t2 = 0;
        for (int e = 0; e < NE; e++) {
            g_offsets[e] = off; g_cursor[e] = off;
            int c = g_counts[e]; off += c;
            g_tp1[e] = t1; g_tp2[e] = t2;
            int rt = (c + ROWT - 1) >> 7;
            t1 += rt * CT1; t2 += rt * CT2;
        }
        g_offsets[NE] = off; g_tp1[NE] = t1; g_tp2[NE] = t2;
    }
}

__global__ __launch_bounds__(256) void k_scatter() {
    int t = blockIdx.x * blockDim.x + threadIdx.x;
    if (t >= T_TOK) return;
#pragma unroll
    for (int s = 0; s < 2; s++) {
        int e = g_te[2 * t + s];
        int pos = atomicAdd(&g_cursor[e], 1);
        g_idx[pos] = t;
        g_wgt[pos] = g_tw[2 * t + s];
        g_pos[2 * t + s] = pos;
    }
}

// ---------------- fp32 -> fp16 convert for weights ----------------
__global__ __launch_bounds__(256) void k_cvt(const float4* __restrict__ src, int which) {
    __half* dst = (which == 1) ? g_gwh : (which == 2) ? g_uwh : g_dwh;
    size_t i = (size_t)blockIdx.x * 256 + threadIdx.x;
    float4 v = src[i];
    __half2 h0 = __floats2half2_rn(v.x, v.y);
    __half2 h1 = __floats2half2_rn(v.z, v.w);
    reinterpret_cast<uint2*>(dst)[i] =
        make_uint2(*reinterpret_cast<uint32_t*>(&h0), *reinterpret_cast<uint32_t*>(&h1));
}

// ---------------- GEMM1: H = silu(X Gw) * (X Uw) ----------------
// CTA: 128 rows x 64 f-cols (gate & up). 8 warps = 2(M) x 4(N); warp tile 64x16.
// 3-stage cp.async pipeline, one barrier per K-tile.
__global__ __launch_bounds__(256, 2) void k_mma1() {
    extern __shared__ __align__(16) char smraw[];
    uint32_t sb = smem_u32(smraw);
    __shared__ int info[3];

    int tid = threadIdx.x, w = tid >> 5, l = tid & 31;
    if (tid == 0) {
        int b = blockIdx.x, e = -1;
        if (b < g_tp1[NE]) {
#pragma unroll
            for (int i = 0; i < NE; i++) if (b < g_tp1[i + 1]) { e = i; break; }
        }
        info[0] = e;
        if (e >= 0) { int t = b - g_tp1[e]; info[1] = (t >> 5) << 7; info[2] = (t & 31) << 6; }
    }
    __syncthreads();
    int e = info[0];
    if (e < 0) return;
    int row0 = info[1], col0 = info[2];
    int off = g_offsets[e], n = g_offsets[e + 1] - off;

    // A gather plan (2 chunks/thread): 128 rows x 32 halves (64B) per K-tile
    const __half* srcA[2]; uint32_t dstA[2];
#pragma unroll
    for (int i = 0; i < 2; i++) {
        int id = tid + i * 256, ar = id >> 2, ch = id & 3;
        int r = row0 + ar; if (r > n - 1) r = n - 1;
        srcA[i] = g_xh + (size_t)g_idx[off + r] * D_DIM + ch * 8;
        dstA[i] = sb + ar * 80 + ch * 16;
    }
    int br = tid >> 3, bc = tid & 7;
    const __half* srcG = g_gwh + ((size_t)e * D_DIM + br) * F_DIM + col0 + bc * 8;
    const __half* srcU = g_uwh + ((size_t)e * D_DIM + br) * F_DIM + col0 + bc * 8;
    uint32_t dstG = sb + 10240 + br * 144 + bc * 16;
    uint32_t dstU = sb + 14848 + br * 144 + bc * 16;

    auto load = [&](int kt) {
        uint32_t s = (uint32_t)(kt % 3) * STG1;
#pragma unroll
        for (int i = 0; i < 2; i++) cpa16(dstA[i] + s, srcA[i] + kt * 32);
        cpa16(dstG + s, srcG + (size_t)kt * 32 * F_DIM);
        cpa16(dstU + s, srcU + (size_t)kt * 32 * F_DIM);
        CP_COMMIT();
    };
    load(0); load(1);

    float cg[4][2][4], cu[4][2][4];
#pragma unroll
    for (int mi = 0; mi < 4; mi++)
#pragma unroll
        for (int ni = 0; ni < 2; ni++)
#pragma unroll
            for (int j = 0; j < 4; j++) { cg[mi][ni][j] = 0.f; cu[mi][ni][j] = 0.f; }

    int wm = w >> 2, wn = w & 3;
    int lr = l & 15, lc = l >> 4;
    uint32_t aOff = (uint32_t)((wm * 64 + lr) * 80 + lc * 16);
    uint32_t gOff = (uint32_t)(10240 + lr * 144 + (wn * 16 + lc * 8) * 2);
    uint32_t uOff = gOff + 4608;

    for (int kt = 0; kt < KT1; kt++) {
        if (kt < KT1 - 1) CP_WAIT(1); else CP_WAIT(0);
        __syncthreads();
        if (kt + 2 < KT1) load(kt + 2);
        uint32_t s = sb + (uint32_t)(kt % 3) * STG1;
#pragma unroll
        for (int ks = 0; ks < 2; ks++) {
            uint32_t a[4][4], bg[4], bu[4];
#pragma unroll
            for (int mi = 0; mi < 4; mi++)
                ldsm4(a[mi], s + aOff + mi * 16 * 80 + ks * 32);
            ldsm4t(bg, s + gOff + ks * 16 * 144);
            ldsm4t(bu, s + uOff + ks * 16 * 144);
#pragma unroll
            for (int mi = 0; mi < 4; mi++)
#pragma unroll
                for (int ni = 0; ni < 2; ni++) {
                    mma16816(cg[mi][ni], a[mi], &bg[2 * ni]);
                    mma16816(cu[mi][ni], a[mi], &bu[2 * ni]);
                }
        }
    }

    // epilogue: h = silu(g) * u, fp16 out
#pragma unroll
    for (int mi = 0; mi < 4; mi++) {
        int rl = row0 + wm * 64 + mi * 16 + (l >> 2);
        int rh = rl + 8;
#pragma unroll
        for (int ni = 0; ni < 2; ni++) {
            int c = col0 + wn * 16 + ni * 8 + 2 * (l & 3);
            float g0 = cg[mi][ni][0], g1 = cg[mi][ni][1], g2 = cg[mi][ni][2], g3 = cg[mi][ni][3];
            float h0 = g0 * __fdividef(1.f, 1.f + __expf(-g0)) * cu[mi][ni][0];
            float h1 = g1 * __fdividef(1.f, 1.f + __expf(-g1)) * cu[mi][ni][1];
            float h2 = g2 * __fdividef(1.f, 1.f + __expf(-g2)) * cu[mi][ni][2];
            float h3 = g3 * __fdividef(1.f, 1.f + __expf(-g3)) * cu[mi][ni][3];
            if (rl < n) *reinterpret_cast<__half2*>(&g_H[(size_t)(off + rl) * F_DIM + c]) = __floats2half2_rn(h0, h1);
            if (rh < n) *reinterpret_cast<__half2*>(&g_H[(size_t)(off + rh) * F_DIM + c]) = __floats2half2_rn(h2, h3);
        }
    }
}

// ---------------- GEMM2: Y = w * (H Dw) ----------------
// CTA: 128 rows x 128 d-cols. 8 warps = 2(M) x 4(N); warp tile 64x32.
__global__ __launch_bounds__(256, 2) void k_mma2() {
    extern __shared__ __align__(16) char smraw[];
    uint32_t sb = smem_u32(smraw);
    __shared__ int info[3];

    int tid = threadIdx.x, w = tid >> 5, l = tid & 31;
    if (tid == 0) {
        int b = blockIdx.x, e = -1;
        if (b < g_tp2[NE]) {
#pragma unroll
            for (int i = 0; i < NE; i++) if (b < g_tp2[i + 1]) { e = i; break; }
        }
        info[0] = e;
        if (e >= 0) { int t = b - g_tp2[e]; info[1] = (t >> 3) << 7; info[2] = (t & 7) << 7; }
    }
    __syncthreads();
    int e = info[0];
    if (e < 0) return;
    int row0 = info[1], col0 = info[2];
    int off = g_offsets[e], n = g_offsets[e + 1] - off;

    const __half* srcA[2]; uint32_t dstA[2];
#pragma unroll
    for (int i = 0; i < 2; i++) {
        int id = tid + i * 256, ar = id >> 2, ch = id & 3;
        int r = row0 + ar; if (r > n - 1) r = n - 1;
        srcA[i] = g_H + (size_t)(off + r) * F_DIM + ch * 8;
        dstA[i] = sb + ar * 80 + ch * 16;
    }
    const __half* srcB[2]; uint32_t dstB[2];
#pragma unroll
    for (int i = 0; i < 2; i++) {
        int id = tid + i * 256, brw = id >> 4, ch = id & 15;
        srcB[i] = g_dwh + ((size_t)e * F_DIM + brw) * D_DIM + col0 + ch * 8;
        dstB[i] = sb + 10240 + brw * 272 + ch * 16;
    }

    auto load = [&](int kt) {
        uint32_t s = (uint32_t)(kt % 3) * STG2;
#pragma unroll
        for (int i = 0; i < 2; i++) cpa16(dstA[i] + s, srcA[i] + kt * 32);
#pragma unroll
        for (int i = 0; i < 2; i++) cpa16(dstB[i] + s, srcB[i] + (size_t)kt * 32 * D_DIM);
        CP_COMMIT();
    };
    load(0); load(1);

    float cc[4][4][4];
#pragma unroll
    for (int mi = 0; mi < 4; mi++)
#pragma unroll
        for (int ni = 0; ni < 4; ni++)
#pragma unroll
            for (int j = 0; j < 4; j++) cc[mi][ni][j] = 0.f;

    int wm = w >> 2, wn = w & 3;
    int lr = l & 15, lc = l >> 4;
    uint32_t aOff = (uint32_t)((wm * 64 + lr) * 80 + lc * 16);
    uint32_t bOff = (uint32_t)(10240 + lr * 272 + (wn * 32 + lc * 8) * 2);

    for (int kt = 0; kt < KT2; kt++) {
        if (kt < KT2 - 1) CP_WAIT(1); else CP_WAIT(0);
        __syncthreads();
        if (kt + 2 < KT2) load(kt + 2);
        uint32_t s = sb + (uint32_t)(kt % 3) * STG2;
#pragma unroll
        for (int ks = 0; ks < 2; ks++) {
            uint32_t a[4][4], bf[2][4];
#pragma unroll
            for (int mi = 0; mi < 4; mi++)
                ldsm4(a[mi], s + aOff + mi * 16 * 80 + ks * 32);
#pragma unroll
            for (int nf = 0; nf < 2; nf++)
                ldsm4t(bf[nf], s + bOff + ks * 16 * 272 + nf * 32);
#pragma unroll
            for (int mi = 0; mi < 4; mi++)
#pragma unroll
                for (int ni = 0; ni < 4; ni++)
                    mma16816(cc[mi][ni], a[mi], &bf[ni >> 1][2 * (ni & 1)]);
        }
    }

#pragma unroll
    for (int mi = 0; mi < 4; mi++) {
        int rl = row0 + wm * 64 + mi * 16 + (l >> 2);
        int rh = rl + 8;
        float wl = (rl < n) ? g_wgt[off + rl] : 0.f;
        float wh = (rh < n) ? g_wgt[off + rh] : 0.f;
#pragma unroll
        for (int ni = 0; ni < 4; ni++) {
            int c = col0 + wn * 32 + ni * 8 + 2 * (l & 3);
            if (rl < n) {
                float2 v = make_float2(wl * cc[mi][ni][0], wl * cc[mi][ni][1]);
                *reinterpret_cast<float2*>(&g_Y[(size_t)(off + rl) * D_DIM + c]) = v;
            }
            if (rh < n) {
                float2 v = make_float2(wh * cc[mi][ni][2], wh * cc[mi][ni][3]);
                *reinterpret_cast<float2*>(&g_Y[(size_t)(off + rh) * D_DIM + c]) = v;
            }
        }
    }
}

// ---------------- combine ----------------
__global__ __launch_bounds__(256) void k_combine(float* __restrict__ out) {
    int gid = blockIdx.x * blockDim.x + threadIdx.x;
    int t = gid >> 8, c = gid & 255;
    if (t >= T_TOK) return;
    int p1 = g_pos[2 * t], p2 = g_pos[2 * t + 1];
    const float4* y = reinterpret_cast<const float4*>(g_Y);
    float4 a = y[(size_t)p1 * (D_DIM / 4) + c];
    float4 b = y[(size_t)p2 * (D_DIM / 4) + c];
    float4 o;
    o.x = a.x + b.x; o.y = a.y + b.y; o.z = a.z + b.z; o.w = a.w + b.w;
    reinterpret_cast<float4*>(out)[gid] = o;
}

// ---------------- launch ----------------
extern "C" void kernel_launch(void* const* d_in, const int* in_sizes, int n_in,
                              void* d_out, int out_size) {
    const float* x  = (const float*)d_in[0];
    const float* rw = (const float*)d_in[1];
    const float* gw = (const float*)d_in[2];
    const float* uw = (const float*)d_in[3];
    const float* dw = (const float*)d_in[4];
    float* out    = (float*)d_out;
    float* logits = out + (size_t)T_TOK * D_DIM;

    static int attr_done = 0;
    if (!attr_done) {
        cudaFuncSetAttribute(k_mma1, cudaFuncAttributeMaxDynamicSharedMemorySize, SMEM1);
        cudaFuncSetAttribute(k_mma2, cudaFuncAttributeMaxDynamicSharedMemorySize, SMEM2);
        attr_done = 1;
    }

    k_init<<<1, 32>>>();
    k_router<<<T_TOK / 8, 256>>>(x, rw, logits);
    k_setup<<<1, 1>>>();
    k_scatter<<<T_TOK / 256, 256>>>();

    k_cvt<<<32768, 256>>>((const float4*)gw, 1);
    k_cvt<<<32768, 256>>>((const float4*)uw, 2);
    k_cvt<<<32768, 256>>>((const float4*)dw, 3);

    k_mma1<<<MAXT1, 256, SMEM1>>>();
    k_mma2<<<MAXT2, 256, SMEM2>>>();
    k_combine<<<(T_TOK * D_DIM / 4) / 256, 256>>>(out);
}

// round 5
// speedup vs baseline: 7.9477x; 1.0644x over previous
#include <cuda_runtime.h>
#include <cuda_fp16.h>
#include <cstdint>
#include <math.h>

#define T_TOK 32768
#define D_DIM 1024
#define F_DIM 2048
#define NE    16
#define NA    (T_TOK * 2)
#define ROWT  128
#define CT1   32                       // F/64 col tiles (gemm1)
#define CT2   8                        // D/128 col tiles (gemm2)
#define KT1   16                       // D/64
#define KT2   32                       // F/64
#define MAXT1 ((NA / ROWT + NE) * CT1)
#define MAXT2 ((NA / ROWT + NE) * CT2)

#define ASZ   18432                    // 128 rows * 144B
#define STG1  (ASZ + 2 * 9216)         // 36864
#define STG2  (ASZ + 17408)            // 35840
#define SMEM1 (3 * STG1)               // 110592
#define SMEM2 (3 * STG2)               // 107520

// ---------------- device scratch ----------------
__device__ int    g_counts[NE];
__device__ int    g_offsets[NE + 1];
__device__ int    g_cursor[NE];
__device__ int    g_te[NA];
__device__ float  g_tw[NA];
__device__ int    g_idx[NA];
__device__ float  g_wgt[NA];
__device__ int    g_pos[NA];
__device__ int    g_tp1[NE + 1];
__device__ int    g_tp2[NE + 1];
__device__ __half g_xh[(size_t)T_TOK * D_DIM];
__device__ __half g_gwh[(size_t)NE * D_DIM * F_DIM];   // [E][D][F]
__device__ __half g_uwh[(size_t)NE * D_DIM * F_DIM];   // [E][D][F]
__device__ __half g_dwh[(size_t)NE * F_DIM * D_DIM];   // [E][F][D]
__device__ __half g_H[(size_t)(NA + ROWT) * F_DIM];
__device__ float  g_Y[(size_t)(NA + ROWT) * D_DIM];

// ---------------- helpers ----------------
__device__ __forceinline__ uint32_t smem_u32(const void* p) {
    uint32_t a;
    asm("{ .reg .u64 t; cvta.to.shared.u64 t, %1; cvt.u32.u64 %0, t; }" : "=r"(a) : "l"(p));
    return a;
}
__device__ __forceinline__ void cpa16(uint32_t s, const void* g) {
    asm volatile("cp.async.cg.shared.global [%0], [%1], 16;" :: "r"(s), "l"(__cvta_generic_to_global(g)) : "memory");
}
#define CP_COMMIT() asm volatile("cp.async.commit_group;" ::: "memory")
#define CP_WAIT(n)  asm volatile("cp.async.wait_group %0;" :: "n"(n) : "memory")

__device__ __forceinline__ void ldsm4(uint32_t* r, uint32_t a) {
    asm volatile("ldmatrix.sync.aligned.m8n8.x4.shared.b16 {%0,%1,%2,%3}, [%4];"
                 : "=r"(r[0]), "=r"(r[1]), "=r"(r[2]), "=r"(r[3]) : "r"(a));
}
__device__ __forceinline__ void ldsm4t(uint32_t* r, uint32_t a) {
    asm volatile("ldmatrix.sync.aligned.m8n8.x4.trans.shared.b16 {%0,%1,%2,%3}, [%4];"
                 : "=r"(r[0]), "=r"(r[1]), "=r"(r[2]), "=r"(r[3]) : "r"(a));
}
__device__ __forceinline__ void mma16816(float* d, const uint32_t* a, const uint32_t* b) {
    asm volatile("mma.sync.aligned.m16n8k16.row.col.f32.f16.f16.f32 "
                 "{%0,%1,%2,%3},{%4,%5,%6,%7},{%8,%9},{%0,%1,%2,%3};"
                 : "+f"(d[0]), "+f"(d[1]), "+f"(d[2]), "+f"(d[3])
                 : "r"(a[0]), "r"(a[1]), "r"(a[2]), "r"(a[3]), "r"(b[0]), "r"(b[1]));
}

// ---------------- routing (+ fused fp16 convert of x) ----------------
__global__ void k_init() { if (threadIdx.x < NE) g_counts[threadIdx.x] = 0; }

__global__ __launch_bounds__(256) void k_router(const float* __restrict__ x,
                                                const float* __restrict__ rw,
                                                float* __restrict__ logits) {
    int warp = (blockIdx.x * blockDim.x + threadIdx.x) >> 5;
    int lane = threadIdx.x & 31;
    if (warp >= T_TOK) return;
    const float* xr = x + (size_t)warp * D_DIM;
    __half* xh = g_xh + (size_t)warp * D_DIM;
    float acc[NE];
#pragma unroll
    for (int e = 0; e < NE; e++) acc[e] = 0.f;
#pragma unroll
    for (int d0 = 0; d0 < D_DIM; d0 += 128) {
        float4 xv = *reinterpret_cast<const float4*>(xr + d0 + lane * 4);
        __half2 h0 = __floats2half2_rn(xv.x, xv.y);
        __half2 h1 = __floats2half2_rn(xv.z, xv.w);
        *reinterpret_cast<uint2*>(xh + d0 + lane * 4) =
            make_uint2(*reinterpret_cast<uint32_t*>(&h0), *reinterpret_cast<uint32_t*>(&h1));
#pragma unroll
        for (int e = 0; e < NE; e++) {
            float4 wv = *reinterpret_cast<const float4*>(rw + e * D_DIM + d0 + lane * 4);
            acc[e] += xv.x * wv.x + xv.y * wv.y + xv.z * wv.z + xv.w * wv.w;
        }
    }
#pragma unroll
    for (int e = 0; e < NE; e++)
#pragma unroll
        for (int off = 16; off > 0; off >>= 1)
            acc[e] += __shfl_down_sync(0xffffffffu, acc[e], off);
    if (lane == 0) {
        float* lo = logits + (size_t)warp * NE;
#pragma unroll
        for (int e = 0; e < NE; e++) lo[e] = acc[e];
        float m = acc[0];
#pragma unroll
        for (int e = 1; e < NE; e++) m = fmaxf(m, acc[e]);
        float p[NE], s = 0.f;
#pragma unroll
        for (int e = 0; e < NE; e++) { p[e] = __expf(acc[e] - m); s += p[e]; }
        float inv = 1.f / s;
        int i1 = 0; float v1 = acc[0];
#pragma unroll
        for (int e = 1; e < NE; e++) if (acc[e] > v1) { v1 = acc[e]; i1 = e; }
        int i2 = -1; float v2 = -1e30f;
#pragma unroll
        for (int e = 0; e < NE; e++) if (e != i1 && acc[e] > v2) { v2 = acc[e]; i2 = e; }
        g_te[2 * warp]     = i1; g_tw[2 * warp]     = p[i1] * inv;
        g_te[2 * warp + 1] = i2; g_tw[2 * warp + 1] = p[i2] * inv;
        atomicAdd(&g_counts[i1], 1);
        atomicAdd(&g_counts[i2], 1);
    }
}

__global__ void k_setup() {
    if (threadIdx.x == 0 && blockIdx.x == 0) {
        int off = 0, t1 = 0, t2 = 0;
        for (int e = 0; e < NE; e++) {
            g_offsets[e] = off; g_cursor[e] = off;
            int c = g_counts[e]; off += c;
            g_tp1[e] = t1; g_tp2[e] = t2;
            int rt = (c + ROWT - 1) >> 7;
            t1 += rt * CT1; t2 += rt * CT2;
        }
        g_offsets[NE] = off; g_tp1[NE] = t1; g_tp2[NE] = t2;
    }
}

__global__ __launch_bounds__(256) void k_scatter() {
    int t = blockIdx.x * blockDim.x + threadIdx.x;
    if (t >= T_TOK) return;
#pragma unroll
    for (int s = 0; s < 2; s++) {
        int e = g_te[2 * t + s];
        int pos = atomicAdd(&g_cursor[e], 1);
        g_idx[pos] = t;
        g_wgt[pos] = g_tw[2 * t + s];
        g_pos[2 * t + s] = pos;
    }
}

// ---------------- fp32 -> fp16 convert for weights ----------------
__global__ __launch_bounds__(256) void k_cvt(const float4* __restrict__ src, int which) {
    __half* dst = (which == 1) ? g_gwh : (which == 2) ? g_uwh : g_dwh;
    size_t i = (size_t)blockIdx.x * 256 + threadIdx.x;
    float4 v = src[i];
    __half2 h0 = __floats2half2_rn(v.x, v.y);
    __half2 h1 = __floats2half2_rn(v.z, v.w);
    reinterpret_cast<uint2*>(dst)[i] =
        make_uint2(*reinterpret_cast<uint32_t*>(&h0), *reinterpret_cast<uint32_t*>(&h1));
}

// ---------------- GEMM1: H = silu(X Gw) * (X Uw) ----------------
// CTA 128 rows x 64 f-cols, K-tile 64, 3-stage cp.async, 1 barrier / tile.
__global__ __launch_bounds__(256, 2) void k_mma1() {
    extern __shared__ __align__(16) char smraw[];
    uint32_t sb = smem_u32(smraw);
    __shared__ int info[3];

    int tid = threadIdx.x, w = tid >> 5, l = tid & 31;
    if (tid == 0) {
        int b = blockIdx.x, e = -1;
        if (b < g_tp1[NE]) {
#pragma unroll
            for (int i = 0; i < NE; i++) if (b < g_tp1[i + 1]) { e = i; break; }
        }
        info[0] = e;
        if (e >= 0) { int t = b - g_tp1[e]; info[1] = (t >> 5) << 7; info[2] = (t & 31) << 6; }
    }
    __syncthreads();
    int e = info[0];
    if (e < 0) return;
    int row0 = info[1], col0 = info[2];
    int off = g_offsets[e], n = g_offsets[e + 1] - off;

    // A gather: 128 rows x 8 chunks(16B) = 1024 chunks, 4/thread
    const __half* srcA[4]; uint32_t dstA[4];
#pragma unroll
    for (int i = 0; i < 4; i++) {
        int id = tid + i * 256, ar = id >> 3, ch = id & 7;
        int r = row0 + ar; if (r > n - 1) r = n - 1;
        srcA[i] = g_xh + (size_t)g_idx[off + r] * D_DIM + ch * 8;
        dstA[i] = sb + ar * 144 + ch * 16;
    }
    // B: 64 k-rows x 8 chunks per tensor = 512 chunks, 2/thread each
    const __half* srcG[2]; const __half* srcU[2]; uint32_t dstB[2];
#pragma unroll
    for (int i = 0; i < 2; i++) {
        int id = tid + i * 256, br = id >> 3, bc = id & 7;
        srcG[i] = g_gwh + ((size_t)e * D_DIM + br) * F_DIM + col0 + bc * 8;
        srcU[i] = g_uwh + ((size_t)e * D_DIM + br) * F_DIM + col0 + bc * 8;
        dstB[i] = sb + ASZ + br * 144 + bc * 16;
    }

    auto load = [&](int kt) {
        uint32_t s = (uint32_t)(kt % 3) * STG1;
        size_t kG = (size_t)kt * 64 * F_DIM;
#pragma unroll
        for (int i = 0; i < 4; i++) cpa16(dstA[i] + s, srcA[i] + kt * 64);
#pragma unroll
        for (int i = 0; i < 2; i++) cpa16(dstB[i] + s, srcG[i] + kG);
#pragma unroll
        for (int i = 0; i < 2; i++) cpa16(dstB[i] + s + 9216, srcU[i] + kG);
        CP_COMMIT();
    };
    load(0); load(1);

    float cg[4][2][4], cu[4][2][4];
#pragma unroll
    for (int mi = 0; mi < 4; mi++)
#pragma unroll
        for (int ni = 0; ni < 2; ni++)
#pragma unroll
            for (int j = 0; j < 4; j++) { cg[mi][ni][j] = 0.f; cu[mi][ni][j] = 0.f; }

    int wm = w >> 2, wn = w & 3;
    int lr = l & 15, lc = l >> 4;
    uint32_t aOff = (uint32_t)((wm * 64 + lr) * 144 + lc * 16);
    uint32_t gOff = (uint32_t)(ASZ + lr * 144 + (wn * 16 + lc * 8) * 2);
    uint32_t uOff = gOff + 9216;

    for (int kt = 0; kt < KT1; kt++) {
        if (kt < KT1 - 1) CP_WAIT(1); else CP_WAIT(0);
        __syncthreads();
        if (kt + 2 < KT1) load(kt + 2);
        uint32_t s = sb + (uint32_t)(kt % 3) * STG1;
#pragma unroll
        for (int ks = 0; ks < 4; ks++) {
            uint32_t a[4][4], bg[4], bu[4];
#pragma unroll
            for (int mi = 0; mi < 4; mi++)
                ldsm4(a[mi], s + aOff + mi * 2304 + ks * 32);
            ldsm4t(bg, s + gOff + ks * 2304);
            ldsm4t(bu, s + uOff + ks * 2304);
#pragma unroll
            for (int mi = 0; mi < 4; mi++)
#pragma unroll
                for (int ni = 0; ni < 2; ni++) {
                    mma16816(cg[mi][ni], a[mi], &bg[2 * ni]);
                    mma16816(cu[mi][ni], a[mi], &bu[2 * ni]);
                }
        }
    }

    // epilogue: h = silu(g) * u, fp16 out
#pragma unroll
    for (int mi = 0; mi < 4; mi++) {
        int rl = row0 + wm * 64 + mi * 16 + (l >> 2);
        int rh = rl + 8;
#pragma unroll
        for (int ni = 0; ni < 2; ni++) {
            int c = col0 + wn * 16 + ni * 8 + 2 * (l & 3);
            float g0 = cg[mi][ni][0], g1 = cg[mi][ni][1], g2 = cg[mi][ni][2], g3 = cg[mi][ni][3];
            float h0 = g0 * __fdividef(1.f, 1.f + __expf(-g0)) * cu[mi][ni][0];
            float h1 = g1 * __fdividef(1.f, 1.f + __expf(-g1)) * cu[mi][ni][1];
            float h2 = g2 * __fdividef(1.f, 1.f + __expf(-g2)) * cu[mi][ni][2];
            float h3 = g3 * __fdividef(1.f, 1.f + __expf(-g3)) * cu[mi][ni][3];
            if (rl < n) *reinterpret_cast<__half2*>(&g_H[(size_t)(off + rl) * F_DIM + c]) = __floats2half2_rn(h0, h1);
            if (rh < n) *reinterpret_cast<__half2*>(&g_H[(size_t)(off + rh) * F_DIM + c]) = __floats2half2_rn(h2, h3);
        }
    }
}

// ---------------- GEMM2: Y = w * (H Dw) ----------------
// CTA 128 rows x 128 d-cols, K-tile 64, 3-stage.
__global__ __launch_bounds__(256, 2) void k_mma2() {
    extern __shared__ __align__(16) char smraw[];
    uint32_t sb = smem_u32(smraw);
    __shared__ int info[3];

    int tid = threadIdx.x, w = tid >> 5, l = tid & 31;
    if (tid == 0) {
        int b = blockIdx.x, e = -1;
        if (b < g_tp2[NE]) {
#pragma unroll
            for (int i = 0; i < NE; i++) if (b < g_tp2[i + 1]) { e = i; break; }
        }
        info[0] = e;
        if (e >= 0) { int t = b - g_tp2[e]; info[1] = (t >> 3) << 7; info[2] = (t & 7) << 7; }
    }
    __syncthreads();
    int e = info[0];
    if (e < 0) return;
    int row0 = info[1], col0 = info[2];
    int off = g_offsets[e], n = g_offsets[e + 1] - off;

    const __half* srcA[4]; uint32_t dstA[4];
#pragma unroll
    for (int i = 0; i < 4; i++) {
        int id = tid + i * 256, ar = id >> 3, ch = id & 7;
        int r = row0 + ar; if (r > n - 1) r = n - 1;
        srcA[i] = g_H + (size_t)(off + r) * F_DIM + ch * 8;
        dstA[i] = sb + ar * 144 + ch * 16;
    }
    // B: 64 k-rows x 16 chunks = 1024 chunks, 4/thread
    const __half* srcB[4]; uint32_t dstB[4];
#pragma unroll
    for (int i = 0; i < 4; i++) {
        int id = tid + i * 256, brw = id >> 4, ch = id & 15;
        srcB[i] = g_dwh + ((size_t)e * F_DIM + brw) * D_DIM + col0 + ch * 8;
        dstB[i] = sb + ASZ + brw * 272 + ch * 16;
    }

    auto load = [&](int kt) {
        uint32_t s = (uint32_t)(kt % 3) * STG2;
        size_t kB = (size_t)kt * 64 * D_DIM;
#pragma unroll
        for (int i = 0; i < 4; i++) cpa16(dstA[i] + s, srcA[i] + kt * 64);
#pragma unroll
        for (int i = 0; i < 4; i++) cpa16(dstB[i] + s, srcB[i] + kB);
        CP_COMMIT();
    };
    load(0); load(1);

    float cc[4][4][4];
#pragma unroll
    for (int mi = 0; mi < 4; mi++)
#pragma unroll
        for (int ni = 0; ni < 4; ni++)
#pragma unroll
            for (int j = 0; j < 4; j++) cc[mi][ni][j] = 0.f;

    int wm = w >> 2, wn = w & 3;
    int lr = l & 15, lc = l >> 4;
    uint32_t aOff = (uint32_t)((wm * 64 + lr) * 144 + lc * 16);
    uint32_t bOff = (uint32_t)(ASZ + lr * 272 + (wn * 32 + lc * 8) * 2);

    for (int kt = 0; kt < KT2; kt++) {
        if (kt < KT2 - 1) CP_WAIT(1); else CP_WAIT(0);
        __syncthreads();
        if (kt + 2 < KT2) load(kt + 2);
        uint32_t s = sb + (uint32_t)(kt % 3) * STG2;
#pragma unroll
        for (int ks = 0; ks < 4; ks++) {
            uint32_t a[4][4], bf[2][4];
#pragma unroll
            for (int mi = 0; mi < 4; mi++)
                ldsm4(a[mi], s + aOff + mi * 2304 + ks * 32);
#pragma unroll
            for (int nf = 0; nf < 2; nf++)
                ldsm4t(bf[nf], s + bOff + ks * 4352 + nf * 32);
#pragma unroll
            for (int mi = 0; mi < 4; mi++)
#pragma unroll
                for (int ni = 0; ni < 4; ni++)
                    mma16816(cc[mi][ni], a[mi], &bf[ni >> 1][2 * (ni & 1)]);
        }
    }

#pragma unroll
    for (int mi = 0; mi < 4; mi++) {
        int rl = row0 + wm * 64 + mi * 16 + (l >> 2);
        int rh = rl + 8;
        float wl = (rl < n) ? g_wgt[off + rl] : 0.f;
        float wh = (rh < n) ? g_wgt[off + rh] : 0.f;
#pragma unroll
        for (int ni = 0; ni < 4; ni++) {
            int c = col0 + wn * 32 + ni * 8 + 2 * (l & 3);
            if (rl < n) {
                float2 v = make_float2(wl * cc[mi][ni][0], wl * cc[mi][ni][1]);
                *reinterpret_cast<float2*>(&g_Y[(size_t)(off + rl) * D_DIM + c]) = v;
            }
            if (rh < n) {
                float2 v = make_float2(wh * cc[mi][ni][2], wh * cc[mi][ni][3]);
                *reinterpret_cast<float2*>(&g_Y[(size_t)(off + rh) * D_DIM + c]) = v;
            }
        }
    }
}

// ---------------- combine ----------------
__global__ __launch_bounds__(256) void k_combine(float* __restrict__ out) {
    int gid = blockIdx.x * blockDim.x + threadIdx.x;
    int t = gid >> 8, c = gid & 255;
    if (t >= T_TOK) return;
    int p1 = g_pos[2 * t], p2 = g_pos[2 * t + 1];
    const float4* y = reinterpret_cast<const float4*>(g_Y);
    float4 a = y[(size_t)p1 * (D_DIM / 4) + c];
    float4 b = y[(size_t)p2 * (D_DIM / 4) + c];
    float4 o;
    o.x = a.x + b.x; o.y = a.y + b.y; o.z = a.z + b.z; o.w = a.w + b.w;
    reinterpret_cast<float4*>(out)[gid] = o;
}

// ---------------- launch ----------------
extern "C" void kernel_launch(void* const* d_in, const int* in_sizes, int n_in,
                              void* d_out, int out_size) {
    const float* x  = (const float*)d_in[0];
    const float* rw = (const float*)d_in[1];
    const float* gw = (const float*)d_in[2];
    const float* uw = (const float*)d_in[3];
    const float* dw = (const float*)d_in[4];
    float* out    = (float*)d_out;
    float* logits = out + (size_t)T_TOK * D_DIM;

    static int attr_done = 0;
    if (!attr_done) {
        cudaFuncSetAttribute(k_mma1, cudaFuncAttributeMaxDynamicSharedMemorySize, SMEM1);
        cudaFuncSetAttribute(k_mma2, cudaFuncAttributeMaxDynamicSharedMemorySize, SMEM2);
        attr_done = 1;
    }

    k_init<<<1, 32>>>();
    k_router<<<T_TOK / 8, 256>>>(x, rw, logits);
    k_setup<<<1, 1>>>();
    k_scatter<<<T_TOK / 256, 256>>>();

    k_cvt<<<32768, 256>>>((const float4*)gw, 1);
    k_cvt<<<32768, 256>>>((const float4*)uw, 2);
    k_cvt<<<32768, 256>>>((const float4*)dw, 3);

    k_mma1<<<MAXT1, 256, SMEM1>>>();
    k_mma2<<<MAXT2, 256, SMEM2>>>();
    k_combine<<<(T_TOK * D_DIM / 4) / 256, 256>>>(out);
}

// round 6
// speedup vs baseline: 7.9640x; 1.0020x over previous
#include <cuda_runtime.h>
#include <cuda_fp16.h>
#include <cstdint>
#include <math.h>

#define T_TOK 32768
#define D_DIM 1024
#define F_DIM 2048
#define NE    16
#define NA    (T_TOK * 2)
#define ROWT  128
#define CT1   32
#define CT2   8
#define KT1   16                       // D/64
#define KT2   32                       // F/64
#define MAXT1 ((NA / ROWT + NE) * CT1)
#define MAXT2 ((NA / ROWT + NE) * CT2)

#define ASZ   18432                    // 128 rows * 144B
#define STG1  (ASZ + 2 * 9216)         // 36864
#define STG2  (ASZ + 17408)            // 35840
#define SMEM1 (3 * STG1)
#define SMEM2 (3 * STG2)

// ---------------- device scratch ----------------
__device__ int    g_counts[NE];
__device__ int    g_offsets[NE + 1];
__device__ int    g_cursor[NE];
__device__ int    g_te[NA];
__device__ float  g_tw[NA];
__device__ int    g_idx[NA];
__device__ float  g_wgt[NA];
__device__ int    g_pos[NA];
__device__ int    g_tp1[NE + 1];
__device__ int    g_tp2[NE + 1];
__device__ __half g_xh[(size_t)T_TOK * D_DIM];
__device__ __half g_gwh[(size_t)NE * D_DIM * F_DIM];
__device__ __half g_uwh[(size_t)NE * D_DIM * F_DIM];
__device__ __half g_dwh[(size_t)NE * F_DIM * D_DIM];
__device__ __half g_H[(size_t)(NA + ROWT) * F_DIM];
__device__ float  g_Y[(size_t)(NA + ROWT) * D_DIM];

// ---------------- helpers ----------------
__device__ __forceinline__ uint32_t smem_u32(const void* p) {
    uint32_t a;
    asm("{ .reg .u64 t; cvta.to.shared.u64 t, %1; cvt.u32.u64 %0, t; }" : "=r"(a) : "l"(p));
    return a;
}
__device__ __forceinline__ void cpa16(uint32_t s, const void* g) {
    asm volatile("cp.async.cg.shared.global [%0], [%1], 16;" :: "r"(s), "l"(__cvta_generic_to_global(g)) : "memory");
}
#define CP_COMMIT() asm volatile("cp.async.commit_group;" ::: "memory")
#define CP_WAIT(n)  asm volatile("cp.async.wait_group %0;" :: "n"(n) : "memory")

__device__ __forceinline__ void ldsm4(uint32_t* r, uint32_t a) {
    asm volatile("ldmatrix.sync.aligned.m8n8.x4.shared.b16 {%0,%1,%2,%3}, [%4];"
                 : "=r"(r[0]), "=r"(r[1]), "=r"(r[2]), "=r"(r[3]) : "r"(a));
}
__device__ __forceinline__ void ldsm4t(uint32_t* r, uint32_t a) {
    asm volatile("ldmatrix.sync.aligned.m8n8.x4.trans.shared.b16 {%0,%1,%2,%3}, [%4];"
                 : "=r"(r[0]), "=r"(r[1]), "=r"(r[2]), "=r"(r[3]) : "r"(a));
}
__device__ __forceinline__ void mma16816(float* d, const uint32_t* a, const uint32_t* b) {
    asm volatile("mma.sync.aligned.m16n8k16.row.col.f32.f16.f16.f32 "
                 "{%0,%1,%2,%3},{%4,%5,%6,%7},{%8,%9},{%0,%1,%2,%3};"
                 : "+f"(d[0]), "+f"(d[1]), "+f"(d[2]), "+f"(d[3])
                 : "r"(a[0]), "r"(a[1]), "r"(a[2]), "r"(a[3]), "r"(b[0]), "r"(b[1]));
}

// ---------------- routing (+ fused fp16 convert of x) ----------------
__global__ void k_init() { if (threadIdx.x < NE) g_counts[threadIdx.x] = 0; }

__global__ __launch_bounds__(256) void k_router(const float* __restrict__ x,
                                                const float* __restrict__ rw,
                                                float* __restrict__ logits) {
    int warp = (blockIdx.x * blockDim.x + threadIdx.x) >> 5;
    int lane = threadIdx.x & 31;
    if (warp >= T_TOK) return;
    const float* xr = x + (size_t)warp * D_DIM;
    __half* xh = g_xh + (size_t)warp * D_DIM;
    float acc[NE];
#pragma unroll
    for (int e = 0; e < NE; e++) acc[e] = 0.f;
#pragma unroll
    for (int d0 = 0; d0 < D_DIM; d0 += 128) {
        float4 xv = *reinterpret_cast<const float4*>(xr + d0 + lane * 4);
        __half2 h0 = __floats2half2_rn(xv.x, xv.y);
        __half2 h1 = __floats2half2_rn(xv.z, xv.w);
        *reinterpret_cast<uint2*>(xh + d0 + lane * 4) =
            make_uint2(*reinterpret_cast<uint32_t*>(&h0), *reinterpret_cast<uint32_t*>(&h1));
#pragma unroll
        for (int e = 0; e < NE; e++) {
            float4 wv = *reinterpret_cast<const float4*>(rw + e * D_DIM + d0 + lane * 4);
            acc[e] += xv.x * wv.x + xv.y * wv.y + xv.z * wv.z + xv.w * wv.w;
        }
    }
#pragma unroll
    for (int e = 0; e < NE; e++)
#pragma unroll
        for (int off = 16; off > 0; off >>= 1)
            acc[e] += __shfl_down_sync(0xffffffffu, acc[e], off);
    if (lane == 0) {
        float* lo = logits + (size_t)warp * NE;
#pragma unroll
        for (int e = 0; e < NE; e++) lo[e] = acc[e];
        float m = acc[0];
#pragma unroll
        for (int e = 1; e < NE; e++) m = fmaxf(m, acc[e]);
        float p[NE], s = 0.f;
#pragma unroll
        for (int e = 0; e < NE; e++) { p[e] = __expf(acc[e] - m); s += p[e]; }
        float inv = 1.f / s;
        int i1 = 0; float v1 = acc[0];
#pragma unroll
        for (int e = 1; e < NE; e++) if (acc[e] > v1) { v1 = acc[e]; i1 = e; }
        int i2 = -1; float v2 = -1e30f;
#pragma unroll
        for (int e = 0; e < NE; e++) if (e != i1 && acc[e] > v2) { v2 = acc[e]; i2 = e; }
        g_te[2 * warp]     = i1; g_tw[2 * warp]     = p[i1] * inv;
        g_te[2 * warp + 1] = i2; g_tw[2 * warp + 1] = p[i2] * inv;
        atomicAdd(&g_counts[i1], 1);
        atomicAdd(&g_counts[i2], 1);
    }
}

__global__ void k_setup() {
    if (threadIdx.x == 0 && blockIdx.x == 0) {
        int off = 0, t1 = 0, t2 = 0;
        for (int e = 0; e < NE; e++) {
            g_offsets[e] = off; g_cursor[e] = off;
            int c = g_counts[e]; off += c;
            g_tp1[e] = t1; g_tp2[e] = t2;
            int rt = (c + ROWT - 1) >> 7;
            t1 += rt * CT1; t2 += rt * CT2;
        }
        g_offsets[NE] = off; g_tp1[NE] = t1; g_tp2[NE] = t2;
    }
}

__global__ __launch_bounds__(256) void k_scatter() {
    int t = blockIdx.x * blockDim.x + threadIdx.x;
    if (t >= T_TOK) return;
#pragma unroll
    for (int s = 0; s < 2; s++) {
        int e = g_te[2 * t + s];
        int pos = atomicAdd(&g_cursor[e], 1);
        g_idx[pos] = t;
        g_wgt[pos] = g_tw[2 * t + s];
        g_pos[2 * t + s] = pos;
    }
}

// ---------------- fp32 -> fp16 weight converts ----------------
// gate+up in one launch (GEMM1 deps); dw separate (GEMM2 dep, hides under GEMM1)
__global__ __launch_bounds__(256) void k_cvt_gu(const float4* __restrict__ gw,
                                                const float4* __restrict__ uw) {
    size_t i = (size_t)blockIdx.x * 256 + threadIdx.x;
    const size_t N4 = (size_t)NE * D_DIM * F_DIM / 4;
    const float4* src = (i < N4) ? gw : uw;
    __half* dst = (i < N4) ? g_gwh : g_uwh;
    size_t j = (i < N4) ? i : i - N4;
    float4 v = src[j];
    __half2 h0 = __floats2half2_rn(v.x, v.y);
    __half2 h1 = __floats2half2_rn(v.z, v.w);
    reinterpret_cast<uint2*>(dst)[j] =
        make_uint2(*reinterpret_cast<uint32_t*>(&h0), *reinterpret_cast<uint32_t*>(&h1));
}
__global__ __launch_bounds__(256) void k_cvt_d(const float4* __restrict__ dw) {
    size_t i = (size_t)blockIdx.x * 256 + threadIdx.x;
    float4 v = dw[i];
    __half2 h0 = __floats2half2_rn(v.x, v.y);
    __half2 h1 = __floats2half2_rn(v.z, v.w);
    reinterpret_cast<uint2*>(g_dwh)[i] =
        make_uint2(*reinterpret_cast<uint32_t*>(&h0), *reinterpret_cast<uint32_t*>(&h1));
}

// ---------------- GEMM1: H = silu(X Gw) * (X Uw) ----------------
__global__ __launch_bounds__(256, 2) void k_mma1() {
    extern __shared__ __align__(16) char smraw[];
    uint32_t sb = smem_u32(smraw);
    __shared__ int info[3];

    int tid = threadIdx.x, w = tid >> 5, l = tid & 31;
    if (tid == 0) {
        int b = blockIdx.x, e = -1;
        if (b < g_tp1[NE]) {
#pragma unroll
            for (int i = 0; i < NE; i++) if (b < g_tp1[i + 1]) { e = i; break; }
        }
        info[0] = e;
        if (e >= 0) { int t = b - g_tp1[e]; info[1] = (t >> 5) << 7; info[2] = (t & 31) << 6; }
    }
    __syncthreads();
    int e = info[0];
    if (e < 0) return;
    int row0 = info[1], col0 = info[2];
    int off = g_offsets[e], n = g_offsets[e + 1] - off;

    const __half* srcA[4]; uint32_t dstA[4];
#pragma unroll
    for (int i = 0; i < 4; i++) {
        int id = tid + i * 256, ar = id >> 3, ch = id & 7;
        int r = row0 + ar; if (r > n - 1) r = n - 1;
        srcA[i] = g_xh + (size_t)g_idx[off + r] * D_DIM + ch * 8;
        dstA[i] = sb + ar * 144 + ch * 16;
    }
    const __half* srcG[2]; const __half* srcU[2]; uint32_t dstB[2];
#pragma unroll
    for (int i = 0; i < 2; i++) {
        int id = tid + i * 256, br = id >> 3, bc = id & 7;
        srcG[i] = g_gwh + ((size_t)e * D_DIM + br) * F_DIM + col0 + bc * 8;
        srcU[i] = g_uwh + ((size_t)e * D_DIM + br) * F_DIM + col0 + bc * 8;
        dstB[i] = sb + ASZ + br * 144 + bc * 16;
    }

    auto load = [&](int kt) {
        uint32_t s = (uint32_t)(kt % 3) * STG1;
        size_t kG = (size_t)kt * 64 * F_DIM;
#pragma unroll
        for (int i = 0; i < 4; i++) cpa16(dstA[i] + s, srcA[i] + kt * 64);
#pragma unroll
        for (int i = 0; i < 2; i++) cpa16(dstB[i] + s, srcG[i] + kG);
#pragma unroll
        for (int i = 0; i < 2; i++) cpa16(dstB[i] + s + 9216, srcU[i] + kG);
        CP_COMMIT();
    };
    load(0); load(1);

    float cg[4][2][4], cu[4][2][4];
#pragma unroll
    for (int mi = 0; mi < 4; mi++)
#pragma unroll
        for (int ni = 0; ni < 2; ni++)
#pragma unroll
            for (int j = 0; j < 4; j++) { cg[mi][ni][j] = 0.f; cu[mi][ni][j] = 0.f; }

    int wm = w >> 2, wn = w & 3;
    int lr = l & 15, lc = l >> 4;
    uint32_t aOff = (uint32_t)((wm * 64 + lr) * 144 + lc * 16);
    uint32_t gOff = (uint32_t)(ASZ + lr * 144 + (wn * 16 + lc * 8) * 2);
    uint32_t uOff = gOff + 9216;

    for (int kt = 0; kt < KT1; kt++) {
        if (kt < KT1 - 1) CP_WAIT(1); else CP_WAIT(0);
        __syncthreads();
        if (kt + 2 < KT1) load(kt + 2);
        uint32_t s = sb + (uint32_t)(kt % 3) * STG1;
#pragma unroll
        for (int ks = 0; ks < 4; ks++) {
            uint32_t a[4][4], bg[4], bu[4];
#pragma unroll
            for (int mi = 0; mi < 4; mi++)
                ldsm4(a[mi], s + aOff + mi * 2304 + ks * 32);
            ldsm4t(bg, s + gOff + ks * 2304);
            ldsm4t(bu, s + uOff + ks * 2304);
#pragma unroll
            for (int mi = 0; mi < 4; mi++)
#pragma unroll
                for (int ni = 0; ni < 2; ni++) {
                    mma16816(cg[mi][ni], a[mi], &bg[2 * ni]);
                    mma16816(cu[mi][ni], a[mi], &bu[2 * ni]);
                }
        }
    }

#pragma unroll
    for (int mi = 0; mi < 4; mi++) {
        int rl = row0 + wm * 64 + mi * 16 + (l >> 2);
        int rh = rl + 8;
#pragma unroll
        for (int ni = 0; ni < 2; ni++) {
            int c = col0 + wn * 16 + ni * 8 + 2 * (l & 3);
            float g0 = cg[mi][ni][0], g1 = cg[mi][ni][1], g2 = cg[mi][ni][2], g3 = cg[mi][ni][3];
            float h0 = g0 * __fdividef(1.f, 1.f + __expf(-g0)) * cu[mi][ni][0];
            float h1 = g1 * __fdividef(1.f, 1.f + __expf(-g1)) * cu[mi][ni][1];
            float h2 = g2 * __fdividef(1.f, 1.f + __expf(-g2)) * cu[mi][ni][2];
            float h3 = g3 * __fdividef(1.f, 1.f + __expf(-g3)) * cu[mi][ni][3];
            if (rl < n) *reinterpret_cast<__half2*>(&g_H[(size_t)(off + rl) * F_DIM + c]) = __floats2half2_rn(h0, h1);
            if (rh < n) *reinterpret_cast<__half2*>(&g_H[(size_t)(off + rh) * F_DIM + c]) = __floats2half2_rn(h2, h3);
        }
    }
}

// ---------------- GEMM2: Y = w * (H Dw) ----------------
__global__ __launch_bounds__(256, 2) void k_mma2() {
    extern __shared__ __align__(16) char smraw[];
    uint32_t sb = smem_u32(smraw);
    __shared__ int info[3];

    int tid = threadIdx.x, w = tid >> 5, l = tid & 31;
    if (tid == 0) {
        int b = blockIdx.x, e = -1;
        if (b < g_tp2[NE]) {
#pragma unroll
            for (int i = 0; i < NE; i++) if (b < g_tp2[i + 1]) { e = i; break; }
        }
        info[0] = e;
        if (e >= 0) { int t = b - g_tp2[e]; info[1] = (t >> 3) << 7; info[2] = (t & 7) << 7; }
    }
    __syncthreads();
    int e = info[0];
    if (e < 0) return;
    int row0 = info[1], col0 = info[2];
    int off = g_offsets[e], n = g_offsets[e + 1] - off;

    const __half* srcA[4]; uint32_t dstA[4];
#pragma unroll
    for (int i = 0; i < 4; i++) {
        int id = tid + i * 256, ar = id >> 3, ch = id & 7;
        int r = row0 + ar; if (r > n - 1) r = n - 1;
        srcA[i] = g_H + (size_t)(off + r) * F_DIM + ch * 8;
        dstA[i] = sb + ar * 144 + ch * 16;
    }
    const __half* srcB[4]; uint32_t dstB[4];
#pragma unroll
    for (int i = 0; i < 4; i++) {
        int id = tid + i * 256, brw = id >> 4, ch = id & 15;
        srcB[i] = g_dwh + ((size_t)e * F_DIM + brw) * D_DIM + col0 + ch * 8;
        dstB[i] = sb + ASZ + brw * 272 + ch * 16;
    }

    auto load = [&](int kt) {
        uint32_t s = (uint32_t)(kt % 3) * STG2;
        size_t kB = (size_t)kt * 64 * D_DIM;
#pragma unroll
        for (int i = 0; i < 4; i++) cpa16(dstA[i] + s, srcA[i] + kt * 64);
#pragma unroll
        for (int i = 0; i < 4; i++) cpa16(dstB[i] + s, srcB[i] + kB);
        CP_COMMIT();
    };
    load(0); load(1);

    float cc[4][4][4];
#pragma unroll
    for (int mi = 0; mi < 4; mi++)
#pragma unroll
        for (int ni = 0; ni < 4; ni++)
#pragma unroll
            for (int j = 0; j < 4; j++) cc[mi][ni][j] = 0.f;

    int wm = w >> 2, wn = w & 3;
    int lr = l & 15, lc = l >> 4;
    uint32_t aOff = (uint32_t)((wm * 64 + lr) * 144 + lc * 16);
    uint32_t bOff = (uint32_t)(ASZ + lr * 272 + (wn * 32 + lc * 8) * 2);

    for (int kt = 0; kt < KT2; kt++) {
        if (kt < KT2 - 1) CP_WAIT(1); else CP_WAIT(0);
        __syncthreads();
        if (kt + 2 < KT2) load(kt + 2);
        uint32_t s = sb + (uint32_t)(kt % 3) * STG2;
#pragma unroll
        for (int ks = 0; ks < 4; ks++) {
            uint32_t a[4][4], bf[2][4];
#pragma unroll
            for (int mi = 0; mi < 4; mi++)
                ldsm4(a[mi], s + aOff + mi * 2304 + ks * 32);
#pragma unroll
            for (int nf = 0; nf < 2; nf++)
                ldsm4t(bf[nf], s + bOff + ks * 4352 + nf * 32);
#pragma unroll
            for (int mi = 0; mi < 4; mi++)
#pragma unroll
                for (int ni = 0; ni < 4; ni++)
                    mma16816(cc[mi][ni], a[mi], &bf[ni >> 1][2 * (ni & 1)]);
        }
    }

#pragma unroll
    for (int mi = 0; mi < 4; mi++) {
        int rl = row0 + wm * 64 + mi * 16 + (l >> 2);
        int rh = rl + 8;
        float wl = (rl < n) ? g_wgt[off + rl] : 0.f;
        float wh = (rh < n) ? g_wgt[off + rh] : 0.f;
#pragma unroll
        for (int ni = 0; ni < 4; ni++) {
            int c = col0 + wn * 32 + ni * 8 + 2 * (l & 3);
            if (rl < n) {
                float2 v = make_float2(wl * cc[mi][ni][0], wl * cc[mi][ni][1]);
                *reinterpret_cast<float2*>(&g_Y[(size_t)(off + rl) * D_DIM + c]) = v;
            }
            if (rh < n) {
                float2 v = make_float2(wh * cc[mi][ni][2], wh * cc[mi][ni][3]);
                *reinterpret_cast<float2*>(&g_Y[(size_t)(off + rh) * D_DIM + c]) = v;
            }
        }
    }
}

// ---------------- combine ----------------
__global__ __launch_bounds__(256) void k_combine(float* __restrict__ out) {
    int gid = blockIdx.x * blockDim.x + threadIdx.x;
    int t = gid >> 8, c = gid & 255;
    if (t >= T_TOK) return;
    int p1 = g_pos[2 * t], p2 = g_pos[2 * t + 1];
    const float4* y = reinterpret_cast<const float4*>(g_Y);
    float4 a = y[(size_t)p1 * (D_DIM / 4) + c];
    float4 b = y[(size_t)p2 * (D_DIM / 4) + c];
    float4 o;
    o.x = a.x + b.x; o.y = a.y + b.y; o.z = a.z + b.z; o.w = a.w + b.w;
    reinterpret_cast<float4*>(out)[gid] = o;
}

// ---------------- launch (fork/join overlap inside graph capture) ----------------
extern "C" void kernel_launch(void* const* d_in, const int* in_sizes, int n_in,
                              void* d_out, int out_size) {
    const float* x  = (const float*)d_in[0];
    const float* rw = (const float*)d_in[1];
    const float* gw = (const float*)d_in[2];
    const float* uw = (const float*)d_in[3];
    const float* dw = (const float*)d_in[4];
    float* out    = (float*)d_out;
    float* logits = out + (size_t)T_TOK * D_DIM;

    static cudaStream_t s1 = nullptr, s2 = nullptr;
    static cudaEvent_t evF = nullptr, ev1 = nullptr, ev2 = nullptr;
    static int init_done = 0;
    if (!init_done) {
        cudaFuncSetAttribute(k_mma1, cudaFuncAttributeMaxDynamicSharedMemorySize, SMEM1);
        cudaFuncSetAttribute(k_mma2, cudaFuncAttributeMaxDynamicSharedMemorySize, SMEM2);
        cudaStreamCreateWithFlags(&s1, cudaStreamNonBlocking);
        cudaStreamCreateWithFlags(&s2, cudaStreamNonBlocking);
        cudaEventCreateWithFlags(&evF, cudaEventDisableTiming);
        cudaEventCreateWithFlags(&ev1, cudaEventDisableTiming);
        cudaEventCreateWithFlags(&ev2, cudaEventDisableTiming);
        init_done = 1;
    }

    // fork: weight conversions run parallel to the routing chain
    cudaEventRecord(evF, 0);
    cudaStreamWaitEvent(s1, evF, 0);
    cudaStreamWaitEvent(s2, evF, 0);
    k_cvt_gu<<<65536, 256, 0, s1>>>((const float4*)gw, (const float4*)uw);
    cudaEventRecord(ev1, s1);
    k_cvt_d<<<32768, 256, 0, s2>>>((const float4*)dw);
    cudaEventRecord(ev2, s2);

    // main: routing chain
    k_init<<<1, 32>>>();
    k_router<<<T_TOK / 8, 256>>>(x, rw, logits);
    k_setup<<<1, 1>>>();
    k_scatter<<<T_TOK / 256, 256>>>();

    // join: GEMM1 needs gate/up fp16; GEMM2 additionally needs down fp16
    cudaStreamWaitEvent(0, ev1, 0);
    k_mma1<<<MAXT1, 256, SMEM1>>>();
    cudaStreamWaitEvent(0, ev2, 0);
    k_mma2<<<MAXT2, 256, SMEM2>>>();
    k_combine<<<(T_TOK * D_DIM / 4) / 256, 256>>>(out);
}